// round 14
// baseline (speedup 1.0000x reference)
#include <cuda_runtime.h>
#include <cuda_bf16.h>
#include <cstdint>
#include <math.h>

#define BSZ 4
#define SEQ 2048
#define EMB 512
#define HEADS 8
#define HD 64
#define HH 512
#define MROWS (BSZ*SEQ)   // 8192
#define NEGINF (-1e30f)

// ---------------------------------------------------------------------------
// Scratch (device globals — no allocation allowed)
// ---------------------------------------------------------------------------
__device__ float g_ol[MROWS*HH];            // unnormalized local attention out
__device__ float g_ml[MROWS*HEADS];         // local row max
__device__ float g_sl[MROWS*HEADS];         // local row sum
__device__ __nv_bfloat16 g_qh[MROWS*HH];
__device__ __nv_bfloat16 g_ql[MROWS*HH];
__device__ __nv_bfloat16 g_kh[MROWS*HH];
__device__ __nv_bfloat16 g_kl[MROWS*HH];
__device__ __nv_bfloat16 g_vh[MROWS*HH];
__device__ __nv_bfloat16 g_vl[MROWS*HH];
__device__ __nv_bfloat16 g_xh[MROWS*EMB];
__device__ __nv_bfloat16 g_xl[MROWS*EMB];
__device__ __nv_bfloat16 g_ah[MROWS*HH];
__device__ __nv_bfloat16 g_al[MROWS*HH];
__device__ __nv_bfloat16 g_wth[4*EMB*HH];   // [wq,wk,wv,wu] transposed [N][K] hi
__device__ __nv_bfloat16 g_wtl[4*EMB*HH];   // lo

// ---------------------------------------------------------------------------
// Helpers (base-ISA only: ldmatrix / mma.sync / cp.async)
// ---------------------------------------------------------------------------
__device__ __forceinline__ uint32_t smem_u32(const void* p) {
    uint32_t a;
    asm("{ .reg .u64 t; cvta.to.shared.u64 t, %1; cvt.u32.u64 %0, t; }"
        : "=r"(a) : "l"(p));
    return a;
}

#define LDSM4(r, addr) \
    asm volatile("ldmatrix.sync.aligned.m8n8.x4.shared.b16 {%0,%1,%2,%3}, [%4];" \
        : "=r"((r)[0]), "=r"((r)[1]), "=r"((r)[2]), "=r"((r)[3]) \
        : "r"(addr))

#define LDSM4T(r, addr) \
    asm volatile("ldmatrix.sync.aligned.m8n8.x4.trans.shared.b16 {%0,%1,%2,%3}, [%4];" \
        : "=r"((r)[0]), "=r"((r)[1]), "=r"((r)[2]), "=r"((r)[3]) \
        : "r"(addr))

__device__ __forceinline__ void mma_bf16(float* d, const uint32_t* a,
                                         uint32_t b0, uint32_t b1) {
    asm volatile(
        "mma.sync.aligned.m16n8k16.row.col.f32.bf16.bf16.f32 "
        "{%0,%1,%2,%3}, {%4,%5,%6,%7}, {%8,%9}, {%0,%1,%2,%3};"
        : "+f"(d[0]), "+f"(d[1]), "+f"(d[2]), "+f"(d[3])
        : "r"(a[0]), "r"(a[1]), "r"(a[2]), "r"(a[3]), "r"(b0), "r"(b1));
}

#define CP_ASYNC16(dst, src) \
    asm volatile("cp.async.cg.shared.global [%0], [%1], 16;" \
                 :: "r"(dst), "l"(src))
#define CP_COMMIT() asm volatile("cp.async.commit_group;")

// ---------------------------------------------------------------------------
// bf16 split conversion (x only)
// ---------------------------------------------------------------------------
__global__ void __launch_bounds__(256) split_bf16_k(
    const float* __restrict__ in, __nv_bfloat16* __restrict__ hi,
    __nv_bfloat16* __restrict__ lo, int n)
{
    int i = (blockIdx.x * 256 + threadIdx.x) * 4;
    if (i >= n) return;
    float4 v = *(const float4*)(in + i);
    __nv_bfloat16 h[4], l[4];
    float vv[4] = {v.x, v.y, v.z, v.w};
    #pragma unroll
    for (int j = 0; j < 4; j++) {
        h[j] = __float2bfloat16(vv[j]);
        l[j] = __float2bfloat16(vv[j] - __bfloat162float(h[j]));
    }
    *(uint2*)(hi + i) = *(uint2*)h;
    *(uint2*)(lo + i) = *(uint2*)l;
}

// ---------------------------------------------------------------------------
// Weight transpose + split
// ---------------------------------------------------------------------------
__global__ void __launch_bounds__(256) wsplit_t(
    const float* __restrict__ w0, const float* __restrict__ w1,
    const float* __restrict__ w2, const float* __restrict__ w3,
    __nv_bfloat16* __restrict__ th, __nv_bfloat16* __restrict__ tl)
{
    __shared__ float t[32][33];
    int z = blockIdx.z;
    const float* W = (z == 0) ? w0 : (z == 1) ? w1 : (z == 2) ? w2 : w3;
    __nv_bfloat16* dh = th + (size_t)z * 512 * 512;
    __nv_bfloat16* dl = tl + (size_t)z * 512 * 512;
    int n0 = blockIdx.x * 32, k0 = blockIdx.y * 32;
    int tx = threadIdx.x & 31, ty = threadIdx.x >> 5;
    #pragma unroll
    for (int i = 0; i < 4; i++) {
        int r = ty + i * 8;
        t[r][tx] = W[(size_t)(k0 + r) * 512 + n0 + tx];
    }
    __syncthreads();
    #pragma unroll
    for (int i = 0; i < 4; i++) {
        int r = ty + i * 8;
        float x = t[tx][r];
        __nv_bfloat16 h = __float2bfloat16(x);
        __nv_bfloat16 l = __float2bfloat16(x - __bfloat162float(h));
        dh[(size_t)(n0 + r) * 512 + k0 + tx] = h;
        dl[(size_t)(n0 + r) * 512 + k0 + tx] = l;
    }
}

// ---------------------------------------------------------------------------
// 256x128 split-precision GEMM tile, 8 warps (4m x 2n), warp tile 64x64.
// SMEM per stage: Ah[256x80B] Al Bh[128x80B] Bl = 61440 B; double-buffered.
// ---------------------------------------------------------------------------
#define BUF2_A  20480              // 256 * 80
#define BUF2_B  10240              // 128 * 80
#define STG2    (2 * BUF2_A + 2 * BUF2_B)   // 61440
#define MMA2_SMEM (2 * STG2)       // 122880

__device__ __forceinline__ void stage_load2(
    uint32_t sdst,
    const __nv_bfloat16* ah, const __nv_bfloat16* al,
    const __nv_bfloat16* bh, const __nv_bfloat16* bl, int tid)
{
    #pragma unroll
    for (int it = 0; it < 4; ++it) {
        int idx = tid + it * 256;
        int r = idx >> 2, seg = idx & 3;
        CP_ASYNC16(sdst + r * 80 + seg * 16,
                   __cvta_generic_to_global(ah + (size_t)r * 512 + seg * 8));
        CP_ASYNC16(sdst + BUF2_A + r * 80 + seg * 16,
                   __cvta_generic_to_global(al + (size_t)r * 512 + seg * 8));
    }
    #pragma unroll
    for (int it = 0; it < 2; ++it) {
        int idx = tid + it * 256;
        int r = idx >> 2, seg = idx & 3;
        CP_ASYNC16(sdst + 2 * BUF2_A + r * 80 + seg * 16,
                   __cvta_generic_to_global(bh + (size_t)r * 512 + seg * 8));
        CP_ASYNC16(sdst + 2 * BUF2_A + BUF2_B + r * 80 + seg * 16,
                   __cvta_generic_to_global(bl + (size_t)r * 512 + seg * 8));
    }
}

// C row stride is 512 for all uses. Bh/Bl already offset to the n-tile.
__device__ __forceinline__ void mma_gemm_256x128(
    const __nv_bfloat16* __restrict__ Ah, const __nv_bfloat16* __restrict__ Al,
    const __nv_bfloat16* __restrict__ Bh, const __nv_bfloat16* __restrict__ Bl,
    float* __restrict__ C, float alpha, const float* __restrict__ bias,
    int m0, int ncol0,
    __nv_bfloat16* __restrict__ Ch, __nv_bfloat16* __restrict__ Cl)
{
    extern __shared__ __align__(16) uint8_t smem[];
    const uint32_t sbase = smem_u32(smem);
    const int tid  = threadIdx.x;
    const int lane = tid & 31, wid = tid >> 5;
    const int wm = wid >> 1, wn = wid & 1;

    const __nv_bfloat16* pAh = Ah + (size_t)m0 * 512;
    const __nv_bfloat16* pAl = Al + (size_t)m0 * 512;

    float acc[4][8][4];
    #pragma unroll
    for (int mf = 0; mf < 4; mf++)
        #pragma unroll
        for (int nf = 0; nf < 8; nf++)
            #pragma unroll
            for (int j = 0; j < 4; j++) acc[mf][nf][j] = 0.f;

    const uint32_t aoff =
        (uint32_t)(wm * 64 + (lane & 15)) * 80 + (lane >> 4) * 16;
    const uint32_t boff =
        (uint32_t)(wn * 64 + (lane & 7) + ((lane >> 3) & 1) * 8) * 80
        + (lane >> 4) * 16;

    stage_load2(sbase, pAh, pAl, Bh, Bl, tid);
    CP_COMMIT();

    for (int c = 0; c < 16; ++c) {
        if (c < 15) {
            stage_load2(sbase + ((c + 1) & 1) * STG2,
                        pAh + (c + 1) * 32, pAl + (c + 1) * 32,
                        Bh + (c + 1) * 32, Bl + (c + 1) * 32, tid);
            CP_COMMIT();
            asm volatile("cp.async.wait_group 1;");
        } else {
            asm volatile("cp.async.wait_group 0;");
        }
        __syncthreads();

        const uint32_t st = sbase + (c & 1) * STG2;
        #pragma unroll
        for (int t = 0; t < 2; ++t) {
            const uint32_t ka = t * 32;
            uint32_t a_h[4][4], a_l[4][4], bb[4][4];

            #pragma unroll
            for (int f = 0; f < 4; ++f) {
                LDSM4(a_h[f], st + aoff + f * 16 * 80 + ka);
                LDSM4(a_l[f], st + BUF2_A + aoff + f * 16 * 80 + ka);
            }
            #pragma unroll
            for (int g = 0; g < 4; ++g)
                LDSM4(bb[g], st + 2 * BUF2_A + boff + g * 16 * 80 + ka);

            // P1: Ah @ Bh
            #pragma unroll
            for (int mf = 0; mf < 4; ++mf)
                #pragma unroll
                for (int nf = 0; nf < 8; ++nf)
                    mma_bf16(acc[mf][nf], a_h[mf],
                             bb[nf >> 1][nf & 1], bb[nf >> 1][2 + (nf & 1)]);
            // P2: Al @ Bh
            #pragma unroll
            for (int mf = 0; mf < 4; ++mf)
                #pragma unroll
                for (int nf = 0; nf < 8; ++nf)
                    mma_bf16(acc[mf][nf], a_l[mf],
                             bb[nf >> 1][nf & 1], bb[nf >> 1][2 + (nf & 1)]);
            // P3: Ah @ Bl
            #pragma unroll
            for (int g = 0; g < 4; ++g)
                LDSM4(bb[g], st + 2 * BUF2_A + BUF2_B + boff + g * 16 * 80 + ka);
            #pragma unroll
            for (int mf = 0; mf < 4; ++mf)
                #pragma unroll
                for (int nf = 0; nf < 8; ++nf)
                    mma_bf16(acc[mf][nf], a_h[mf],
                             bb[nf >> 1][nf & 1], bb[nf >> 1][2 + (nf & 1)]);
        }
        __syncthreads();
    }

    #pragma unroll
    for (int mf = 0; mf < 4; ++mf) {
        const int r0 = m0 + wm * 64 + mf * 16 + (lane >> 2);
        #pragma unroll
        for (int nf = 0; nf < 8; ++nf) {
            const int col = ncol0 + wn * 64 + nf * 8 + (lane & 3) * 2;
            float bx = 0.f, by = 0.f;
            if (bias) { bx = bias[col]; by = bias[col + 1]; }
            float2 v0 = make_float2(acc[mf][nf][0] * alpha + bx,
                                    acc[mf][nf][1] * alpha + by);
            float2 v1 = make_float2(acc[mf][nf][2] * alpha + bx,
                                    acc[mf][nf][3] * alpha + by);
            if (C) {
                *(float2*)(C + (size_t)r0 * 512 + col) = v0;
                *(float2*)(C + (size_t)(r0 + 8) * 512 + col) = v1;
            }
            if (Ch) {
                __nv_bfloat162 hh, ll;
                hh.x = __float2bfloat16(v0.x);
                hh.y = __float2bfloat16(v0.y);
                ll.x = __float2bfloat16(v0.x - __bfloat162float(hh.x));
                ll.y = __float2bfloat16(v0.y - __bfloat162float(hh.y));
                *(__nv_bfloat162*)(Ch + (size_t)r0 * 512 + col) = hh;
                *(__nv_bfloat162*)(Cl + (size_t)r0 * 512 + col) = ll;
                hh.x = __float2bfloat16(v1.x);
                hh.y = __float2bfloat16(v1.y);
                ll.x = __float2bfloat16(v1.x - __bfloat162float(hh.x));
                ll.y = __float2bfloat16(v1.y - __bfloat162float(hh.y));
                *(__nv_bfloat162*)(Ch + (size_t)(r0 + 8) * 512 + col) = hh;
                *(__nv_bfloat162*)(Cl + (size_t)(r0 + 8) * 512 + col) = ll;
            }
        }
    }
}

// Fused Q/K/V projection as one 8192 x 1536 x 512 GEMM; grid (12, 32).
__global__ void __launch_bounds__(256) proj_mma(
    const __nv_bfloat16* __restrict__ xh, const __nv_bfloat16* __restrict__ xl,
    const __nv_bfloat16* __restrict__ wth, const __nv_bfloat16* __restrict__ wtl,
    __nv_bfloat16* qh, __nv_bfloat16* ql,
    __nv_bfloat16* kh, __nv_bfloat16* kl,
    __nv_bfloat16* vh, __nv_bfloat16* vl)
{
    int z = blockIdx.x >> 2;                     // which weight/output
    int nloc = (blockIdx.x & 3) * 128;           // n-tile within the tensor
    const __nv_bfloat16* bh = wth + (size_t)z * 512 * 512 + (size_t)nloc * 512;
    const __nv_bfloat16* bl = wtl + (size_t)z * 512 * 512 + (size_t)nloc * 512;
    __nv_bfloat16* Ch = (z == 0) ? qh : (z == 1) ? kh : vh;
    __nv_bfloat16* Cl = (z == 0) ? ql : (z == 1) ? kl : vl;
    float alpha = (z == 2) ? 1.0f : 0.125f;      // 64^-0.5 on q and k
    mma_gemm_256x128(xh, xl, bh, bl, nullptr, alpha, nullptr,
                     blockIdx.y * 256, nloc, Ch, Cl);
}

// Unify: 8192 x 512 x 512 GEMM; grid (4, 32).
__global__ void __launch_bounds__(256) unify_mma(
    const __nv_bfloat16* __restrict__ ah, const __nv_bfloat16* __restrict__ al,
    const __nv_bfloat16* __restrict__ wth, const __nv_bfloat16* __restrict__ wtl,
    float* __restrict__ out, const float* __restrict__ bias)
{
    int nloc = blockIdx.x * 128;
    mma_gemm_256x128(ah, al,
                     wth + 3ull * 512 * 512 + (size_t)nloc * 512,
                     wtl + 3ull * 512 * 512 + (size_t)nloc * 512,
                     out, 1.0f, bias, blockIdx.y * 256, nloc,
                     nullptr, nullptr);
}

// ---------------------------------------------------------------------------
// Local-window attention (HMMA). Writes UNNORMALIZED O_local (fp32) + per-row
// (max, sum). Strided part handled by attn_strided.
// ---------------------------------------------------------------------------
#define SM_QH      0         // 64 x 72 bf16 (stride 144B)
#define SM_QL      9216
#define SM_KH      18432     // 128 x 72 bf16 | later Ph 64 x 136 bf16 (272B)
#define SM_KL      36864     // 128 x 72 bf16 | later Pl
#define SM_VH      55296     // 128 x 72 bf16
#define SM_VL      73728
#define SM_REDMAX  92160     // fp32 [64][4]
#define SM_REDSUM  93184     // fp32 [64][4]
#define ATTN_SMEM  94208

__global__ void __launch_bounds__(256, 2) attn_local(
    const __nv_bfloat16* __restrict__ qh, const __nv_bfloat16* __restrict__ ql,
    const __nv_bfloat16* __restrict__ kh, const __nv_bfloat16* __restrict__ kl,
    const __nv_bfloat16* __restrict__ vh, const __nv_bfloat16* __restrict__ vl,
    float* __restrict__ Ol, float* __restrict__ Ml, float* __restrict__ Sl)
{
    extern __shared__ __align__(16) char smraw[];
    const uint32_t sb = smem_u32(smraw);
    const int qt   = blockIdx.x;
    const int h    = blockIdx.y;
    const int b    = blockIdx.z;
    const int base = qt * 64;
    const int tid  = threadIdx.x;
    const int lane = tid & 31, wid = tid >> 5;
    const int wm = wid >> 2, wn = wid & 3;

    float* REDMAX = (float*)(smraw + SM_REDMAX);
    float* REDSUM = (float*)(smraw + SM_REDSUM);

    #define ROWOFF(p) ((size_t)((b * SEQ + (p)) * HEADS + h) * HD)

    // stage Q hi/lo
    for (int idx = tid; idx < 1024; idx += 256) {
        int buf = idx >> 9, rem = idx & 511;
        int i = rem >> 3, seg = rem & 7;
        const __nv_bfloat16* src = (buf ? ql : qh) + ROWOFF(base + i) + seg * 8;
        CP_ASYNC16(sb + SM_QH + buf * 9216 + i * 144 + seg * 16,
                   __cvta_generic_to_global(src));
    }
    // stage K/V window hi/lo
    for (int idx = tid; idx < 4096; idx += 256) {
        int buf = idx >> 10, rem = idx & 1023;
        int t = rem >> 3, seg = rem & 7;
        int key = base - 64 + t;
        uint32_t dstoff = (buf == 0 ? SM_KH : buf == 1 ? SM_KL :
                           buf == 2 ? SM_VH : SM_VL) + t * 144 + seg * 16;
        if (key >= 0) {
            const __nv_bfloat16* src =
                (buf == 0 ? kh : buf == 1 ? kl : buf == 2 ? vh : vl)
                + ROWOFF(key) + seg * 8;
            CP_ASYNC16(sb + dstoff, __cvta_generic_to_global(src));
        } else {
            *(uint4*)(smraw + dstoff) = make_uint4(0, 0, 0, 0);
        }
    }
    CP_COMMIT();
    asm volatile("cp.async.wait_group 0;");
    __syncthreads();

    // S = Q @ Kwin^T (3 split passes)
    float accs[2][4][4];
    #pragma unroll
    for (int mf = 0; mf < 2; mf++)
        #pragma unroll
        for (int nf = 0; nf < 4; nf++)
            #pragma unroll
            for (int j = 0; j < 4; j++) accs[mf][nf][j] = 0.f;

    const uint32_t aQrow = (uint32_t)(wm * 32 + (lane & 15)) * 144
                         + (lane >> 4) * 16;
    const uint32_t bKrow = (uint32_t)(wn * 32 + (lane & 7)
                         + ((lane >> 3) & 1) * 8) * 144 + (lane >> 4) * 16;

    #pragma unroll
    for (int kd = 0; kd < 4; kd++) {
        const uint32_t ka = kd * 32;
        uint32_t a_h[2][4], a_l[2][4], bh4[2][4], bl4[2][4];
        LDSM4(a_h[0], sb + SM_QH + aQrow + ka);
        LDSM4(a_h[1], sb + SM_QH + aQrow + 16 * 144 + ka);
        LDSM4(a_l[0], sb + SM_QL + aQrow + ka);
        LDSM4(a_l[1], sb + SM_QL + aQrow + 16 * 144 + ka);
        #pragma unroll
        for (int g = 0; g < 2; g++) {
            LDSM4(bh4[g], sb + SM_KH + bKrow + g * 16 * 144 + ka);
            LDSM4(bl4[g], sb + SM_KL + bKrow + g * 16 * 144 + ka);
        }
        #pragma unroll
        for (int mf = 0; mf < 2; mf++)
            #pragma unroll
            for (int nf = 0; nf < 4; nf++) {
                mma_bf16(accs[mf][nf], a_h[mf],
                         bh4[nf >> 1][nf & 1], bh4[nf >> 1][2 + (nf & 1)]);
                mma_bf16(accs[mf][nf], a_l[mf],
                         bh4[nf >> 1][nf & 1], bh4[nf >> 1][2 + (nf & 1)]);
                mma_bf16(accs[mf][nf], a_h[mf],
                         bl4[nf >> 1][nf & 1], bl4[nf >> 1][2 + (nf & 1)]);
            }
    }

    // mask + per-warp row max
    #pragma unroll
    for (int mf = 0; mf < 2; mf++)
        #pragma unroll
        for (int rh = 0; rh < 2; rh++) {
            int q_l = wm * 32 + mf * 16 + rh * 8 + (lane >> 2);
            int tlo = (base == 0) ? 64 : q_l;
            int thi = q_l + 64;
            float m = NEGINF;
            #pragma unroll
            for (int nf = 0; nf < 4; nf++)
                #pragma unroll
                for (int c = 0; c < 2; c++) {
                    int t = wn * 32 + nf * 8 + (lane & 3) * 2 + c;
                    float& sv = accs[mf][nf][rh * 2 + c];
                    if (t < tlo || t > thi) sv = NEGINF;
                    m = fmaxf(m, sv);
                }
            m = fmaxf(m, __shfl_xor_sync(0xffffffffu, m, 1));
            m = fmaxf(m, __shfl_xor_sync(0xffffffffu, m, 2));
            if ((lane & 3) == 0) REDMAX[q_l * 4 + wn] = m;
        }
    __syncthreads();   // B1

    // exp fragments -> P bf16 hi/lo; row sums
    #pragma unroll
    for (int mf = 0; mf < 2; mf++)
        #pragma unroll
        for (int rh = 0; rh < 2; rh++) {
            int q_l = wm * 32 + mf * 16 + rh * 8 + (lane >> 2);
            float Mr = fmaxf(fmaxf(REDMAX[q_l * 4 + 0], REDMAX[q_l * 4 + 1]),
                             fmaxf(REDMAX[q_l * 4 + 2], REDMAX[q_l * 4 + 3]));
            float rsum = 0.f;
            #pragma unroll
            for (int nf = 0; nf < 4; nf++) {
                float p0 = __expf(accs[mf][nf][rh * 2 + 0] - Mr);
                float p1 = __expf(accs[mf][nf][rh * 2 + 1] - Mr);
                rsum += p0 + p1;
                int t0 = wn * 32 + nf * 8 + (lane & 3) * 2;
                uint32_t addr = (uint32_t)q_l * 272 + t0 * 2;
                __nv_bfloat162 hh, ll;
                hh.x = __float2bfloat16(p0);
                hh.y = __float2bfloat16(p1);
                ll.x = __float2bfloat16(p0 - __bfloat162float(hh.x));
                ll.y = __float2bfloat16(p1 - __bfloat162float(hh.y));
                *(__nv_bfloat162*)(smraw + SM_KH + addr) = hh;
                *(__nv_bfloat162*)(smraw + SM_KL + addr) = ll;
            }
            rsum += __shfl_xor_sync(0xffffffffu, rsum, 1);
            rsum += __shfl_xor_sync(0xffffffffu, rsum, 2);
            if ((lane & 3) == 0) REDSUM[q_l * 4 + wn] = rsum;
        }
    __syncthreads();   // B2

    // O = P @ Vwin (3 split passes)
    float acco[2][2][4];
    #pragma unroll
    for (int mf = 0; mf < 2; mf++)
        #pragma unroll
        for (int nf = 0; nf < 2; nf++)
            #pragma unroll
            for (int j = 0; j < 4; j++) acco[mf][nf][j] = 0.f;

    const uint32_t aProw = (uint32_t)(wm * 32 + (lane & 15)) * 272
                         + (lane >> 4) * 16;
    const uint32_t bVcol = (uint32_t)(wn * 16 + (lane >> 4) * 8) * 2;

    #pragma unroll
    for (int kt = 0; kt < 8; kt++) {
        uint32_t pa_h[2][4], pa_l[2][4], vbh[4], vbl[4];
        LDSM4(pa_h[0], sb + SM_KH + aProw + kt * 32);
        LDSM4(pa_h[1], sb + SM_KH + aProw + 16 * 272 + kt * 32);
        LDSM4(pa_l[0], sb + SM_KL + aProw + kt * 32);
        LDSM4(pa_l[1], sb + SM_KL + aProw + 16 * 272 + kt * 32);
        uint32_t vrow = (uint32_t)(kt * 16 + (lane & 15)) * 144 + bVcol;
        LDSM4T(vbh, sb + SM_VH + vrow);
        LDSM4T(vbl, sb + SM_VL + vrow);
        #pragma unroll
        for (int mf = 0; mf < 2; mf++) {
            mma_bf16(acco[mf][0], pa_h[mf], vbh[0], vbh[1]);
            mma_bf16(acco[mf][1], pa_h[mf], vbh[2], vbh[3]);
            mma_bf16(acco[mf][0], pa_h[mf], vbl[0], vbl[1]);
            mma_bf16(acco[mf][1], pa_h[mf], vbl[2], vbl[3]);
            mma_bf16(acco[mf][0], pa_l[mf], vbh[0], vbh[1]);
            mma_bf16(acco[mf][1], pa_l[mf], vbh[2], vbh[3]);
        }
    }

    // epilogue: write unnormalized O_local + per-row (max, sum)
    const int d0 = wn * 16 + (lane & 3) * 2;
    #pragma unroll
    for (int mf = 0; mf < 2; mf++)
        #pragma unroll
        for (int rh = 0; rh < 2; rh++) {
            int q_l = wm * 32 + mf * 16 + rh * 8 + (lane >> 2);
            int qpos = base + q_l;
            if (wn == 0 && (lane & 3) == 0) {
                float Mr = fmaxf(fmaxf(REDMAX[q_l * 4 + 0], REDMAX[q_l * 4 + 1]),
                                 fmaxf(REDMAX[q_l * 4 + 2], REDMAX[q_l * 4 + 3]));
                float sum = REDSUM[q_l * 4 + 0] + REDSUM[q_l * 4 + 1]
                          + REDSUM[q_l * 4 + 2] + REDSUM[q_l * 4 + 3];
                int gi = (b * SEQ + qpos) * HEADS + h;
                Ml[gi] = Mr;
                Sl[gi] = sum;
            }
            size_t off = ROWOFF(qpos) + d0;
            *(float2*)(Ol + off) =
                make_float2(acco[mf][0][rh * 2 + 0], acco[mf][0][rh * 2 + 1]);
            *(float2*)(Ol + off + 8) =
                make_float2(acco[mf][1][rh * 2 + 0], acco[mf][1][rh * 2 + 1]);
        }
    #undef ROWOFF
}

// ---------------------------------------------------------------------------
// Strided attention + flash-combine. Block = (residue r, head, batch).
// ---------------------------------------------------------------------------
#define ST_QH    0       // 32 x 72 bf16 (144B stride)
#define ST_QL    4608
#define ST_KH    9216
#define ST_KL    13824
#define ST_VH    18432
#define ST_VL    23040
#define ST_PH    27648   // 32 x 40 bf16 (80B stride)
#define ST_PL    30208
#define ST_RMAX  32768   // fp32 [32][4]
#define ST_RSUM  33280   // fp32 [32][4]
#define ST_TOTAL 33792

__global__ void __launch_bounds__(128) attn_strided(
    const __nv_bfloat16* __restrict__ qh, const __nv_bfloat16* __restrict__ ql,
    const __nv_bfloat16* __restrict__ kh, const __nv_bfloat16* __restrict__ kl,
    const __nv_bfloat16* __restrict__ vh, const __nv_bfloat16* __restrict__ vl,
    const float* __restrict__ Ol, const float* __restrict__ Ml,
    const float* __restrict__ Sl,
    __nv_bfloat16* __restrict__ outh, __nv_bfloat16* __restrict__ outl)
{
    __shared__ __align__(16) char ss[ST_TOTAL];
    const uint32_t sb = smem_u32(ss);
    const int r = blockIdx.x, h = blockIdx.y, b = blockIdx.z;
    const int tid = threadIdx.x, lane = tid & 31, wn = tid >> 5;

    float* RMAX = (float*)(ss + ST_RMAX);
    float* RSUM = (float*)(ss + ST_RSUM);

    #define ROWOFF(p) ((size_t)((b * SEQ + (p)) * HEADS + h) * HD)

    for (int idx = tid; idx < 1536; idx += 128) {
        int buf = idx >> 8, rem = idx & 255;
        int j = rem >> 3, seg = rem & 7;
        const __nv_bfloat16* bp =
            buf == 0 ? qh : buf == 1 ? ql : buf == 2 ? kh :
            buf == 3 ? kl : buf == 4 ? vh : vl;
        CP_ASYNC16(sb + buf * 4608 + j * 144 + seg * 16,
                   __cvta_generic_to_global(bp + ROWOFF(64 * j + r) + seg * 8));
    }
    CP_COMMIT();
    asm volatile("cp.async.wait_group 0;");
    __syncthreads();

    float accs[2][4];
    #pragma unroll
    for (int mf = 0; mf < 2; mf++)
        #pragma unroll
        for (int j = 0; j < 4; j++) accs[mf][j] = 0.f;

    const uint32_t aQrow = (uint32_t)(lane & 15) * 144 + (lane >> 4) * 16;
    const uint32_t bKrow = (uint32_t)(wn * 8 + (lane & 7)) * 144
                         + (lane >> 3) * 16;

    uint32_t bh4[2][4], bl4[2][4];
    LDSM4(bh4[0], sb + ST_KH + bKrow);
    LDSM4(bh4[1], sb + ST_KH + bKrow + 64);
    LDSM4(bl4[0], sb + ST_KL + bKrow);
    LDSM4(bl4[1], sb + ST_KL + bKrow + 64);

    #pragma unroll
    for (int kd = 0; kd < 4; kd++) {
        uint32_t a_h[2][4], a_l[2][4];
        LDSM4(a_h[0], sb + ST_QH + aQrow + kd * 32);
        LDSM4(a_h[1], sb + ST_QH + aQrow + 16 * 144 + kd * 32);
        LDSM4(a_l[0], sb + ST_QL + aQrow + kd * 32);
        LDSM4(a_l[1], sb + ST_QL + aQrow + 16 * 144 + kd * 32);
        uint32_t b0h = bh4[kd >> 1][(kd & 1) * 2];
        uint32_t b1h = bh4[kd >> 1][(kd & 1) * 2 + 1];
        uint32_t b0l = bl4[kd >> 1][(kd & 1) * 2];
        uint32_t b1l = bl4[kd >> 1][(kd & 1) * 2 + 1];
        #pragma unroll
        for (int mf = 0; mf < 2; mf++) {
            mma_bf16(accs[mf], a_h[mf], b0h, b1h);
            mma_bf16(accs[mf], a_l[mf], b0h, b1h);
            mma_bf16(accs[mf], a_h[mf], b0l, b1l);
        }
    }

    #pragma unroll
    for (int mf = 0; mf < 2; mf++)
        #pragma unroll
        for (int rh = 0; rh < 2; rh++) {
            int j = mf * 16 + rh * 8 + (lane >> 2);
            float m = NEGINF;
            #pragma unroll
            for (int c = 0; c < 2; c++) {
                int i = wn * 8 + (lane & 3) * 2 + c;
                float& sv = accs[mf][rh * 2 + c];
                if (i > j - 2) sv = NEGINF;
                m = fmaxf(m, sv);
            }
            m = fmaxf(m, __shfl_xor_sync(0xffffffffu, m, 1));
            m = fmaxf(m, __shfl_xor_sync(0xffffffffu, m, 2));
            if ((lane & 3) == 0) RMAX[j * 4 + wn] = m;
        }
    __syncthreads();

    #pragma unroll
    for (int mf = 0; mf < 2; mf++)
        #pragma unroll
        for (int rh = 0; rh < 2; rh++) {
            int j = mf * 16 + rh * 8 + (lane >> 2);
            float Ms = fmaxf(fmaxf(RMAX[j * 4 + 0], RMAX[j * 4 + 1]),
                             fmaxf(RMAX[j * 4 + 2], RMAX[j * 4 + 3]));
            int i0 = wn * 8 + (lane & 3) * 2;
            float p0 = (i0 <= j - 2)
                     ? __expf(accs[mf][rh * 2 + 0] - Ms) : 0.f;
            float p1 = (i0 + 1 <= j - 2)
                     ? __expf(accs[mf][rh * 2 + 1] - Ms) : 0.f;
            float rsum = p0 + p1;
            uint32_t addr = (uint32_t)j * 80 + i0 * 2;
            __nv_bfloat162 hh, ll;
            hh.x = __float2bfloat16(p0);
            hh.y = __float2bfloat16(p1);
            ll.x = __float2bfloat16(p0 - __bfloat162float(hh.x));
            ll.y = __float2bfloat16(p1 - __bfloat162float(hh.y));
            *(__nv_bfloat162*)(ss + ST_PH + addr) = hh;
            *(__nv_bfloat162*)(ss + ST_PL + addr) = ll;
            rsum += __shfl_xor_sync(0xffffffffu, rsum, 1);
            rsum += __shfl_xor_sync(0xffffffffu, rsum, 2);
            if ((lane & 3) == 0) RSUM[j * 4 + wn] = rsum;
        }
    __syncthreads();

    float acco[2][2][4];
    #pragma unroll
    for (int mf = 0; mf < 2; mf++)
        #pragma unroll
        for (int nf = 0; nf < 2; nf++)
            #pragma unroll
            for (int j = 0; j < 4; j++) acco[mf][nf][j] = 0.f;

    const uint32_t aProw = (uint32_t)(lane & 15) * 80 + (lane >> 4) * 16;
    const uint32_t bVcol = (uint32_t)(wn * 16 + (lane >> 4) * 8) * 2;

    #pragma unroll
    for (int kt = 0; kt < 2; kt++) {
        uint32_t pa_h[2][4], pa_l[2][4], vbh[4], vbl[4];
        LDSM4(pa_h[0], sb + ST_PH + aProw + kt * 32);
        LDSM4(pa_h[1], sb + ST_PH + aProw + 16 * 80 + kt * 32);
        LDSM4(pa_l[0], sb + ST_PL + aProw + kt * 32);
        LDSM4(pa_l[1], sb + ST_PL + aProw + 16 * 80 + kt * 32);
        uint32_t vrow = (uint32_t)(kt * 16 + (lane & 15)) * 144 + bVcol;
        LDSM4T(vbh, sb + ST_VH + vrow);
        LDSM4T(vbl, sb + ST_VL + vrow);
        #pragma unroll
        for (int mf = 0; mf < 2; mf++) {
            mma_bf16(acco[mf][0], pa_h[mf], vbh[0], vbh[1]);
            mma_bf16(acco[mf][1], pa_h[mf], vbh[2], vbh[3]);
            mma_bf16(acco[mf][0], pa_h[mf], vbl[0], vbl[1]);
            mma_bf16(acco[mf][1], pa_h[mf], vbl[2], vbl[3]);
            mma_bf16(acco[mf][0], pa_l[mf], vbh[0], vbh[1]);
            mma_bf16(acco[mf][1], pa_l[mf], vbh[2], vbh[3]);
        }
    }

    #pragma unroll
    for (int mf = 0; mf < 2; mf++)
        #pragma unroll
        for (int rh = 0; rh < 2; rh++) {
            int j = mf * 16 + rh * 8 + (lane >> 2);
            int qpos = 64 * j + r;
            float m_s = fmaxf(fmaxf(RMAX[j * 4 + 0], RMAX[j * 4 + 1]),
                              fmaxf(RMAX[j * 4 + 2], RMAX[j * 4 + 3]));
            float s_s = RSUM[j * 4 + 0] + RSUM[j * 4 + 1]
                      + RSUM[j * 4 + 2] + RSUM[j * 4 + 3];
            int gi = (b * SEQ + qpos) * HEADS + h;
            float m_l = Ml[gi], s_l = Sl[gi];
            float M = fmaxf(m_l, m_s);
            float fl = __expf(m_l - M);
            float fs = __expf(m_s - M);
            float inv = 1.f / (s_l * fl + s_s * fs);
            #pragma unroll
            for (int nf = 0; nf < 2; nf++) {
                int d0 = wn * 16 + nf * 8 + (lane & 3) * 2;
                size_t off = ROWOFF(qpos) + d0;
                float2 olv = *(const float2*)(Ol + off);
                float o0 = (olv.x * fl + acco[mf][nf][rh * 2 + 0] * fs) * inv;
                float o1 = (olv.y * fl + acco[mf][nf][rh * 2 + 1] * fs) * inv;
                __nv_bfloat162 hh, ll;
                hh.x = __float2bfloat16(o0);
                hh.y = __float2bfloat16(o1);
                ll.x = __float2bfloat16(o0 - __bfloat162float(hh.x));
                ll.y = __float2bfloat16(o1 - __bfloat162float(hh.y));
                *(__nv_bfloat162*)(outh + off) = hh;
                *(__nv_bfloat162*)(outl + off) = ll;
            }
        }
    #undef ROWOFF
}

// ---------------------------------------------------------------------------
extern "C" void kernel_launch(void* const* d_in, const int* in_sizes, int n_in,
                              void* d_out, int out_size)
{
    const float* x  = (const float*)d_in[0];
    const float* wk = (const float*)d_in[1];
    const float* wq = (const float*)d_in[2];
    const float* wv = (const float*)d_in[3];
    const float* wu = (const float*)d_in[4];
    const float* bu = (const float*)d_in[5];
    float* out = (float*)d_out;

    float *ol, *ml, *sl;
    __nv_bfloat16 *xh, *xl, *ah, *al, *wth, *wtl;
    __nv_bfloat16 *qh, *ql, *kh, *kl, *vh, *vl;
    cudaGetSymbolAddress((void**)&ol,  g_ol);
    cudaGetSymbolAddress((void**)&ml,  g_ml);
    cudaGetSymbolAddress((void**)&sl,  g_sl);
    cudaGetSymbolAddress((void**)&xh,  g_xh);
    cudaGetSymbolAddress((void**)&xl,  g_xl);
    cudaGetSymbolAddress((void**)&ah,  g_ah);
    cudaGetSymbolAddress((void**)&al,  g_al);
    cudaGetSymbolAddress((void**)&wth, g_wth);
    cudaGetSymbolAddress((void**)&wtl, g_wtl);
    cudaGetSymbolAddress((void**)&qh,  g_qh);
    cudaGetSymbolAddress((void**)&ql,  g_ql);
    cudaGetSymbolAddress((void**)&kh,  g_kh);
    cudaGetSymbolAddress((void**)&kl,  g_kl);
    cudaGetSymbolAddress((void**)&vh,  g_vh);
    cudaGetSymbolAddress((void**)&vl,  g_vl);

    // 1) split x; transpose+split weights
    split_bf16_k<<<(MROWS * EMB) / 1024, 256>>>(x, xh, xl, MROWS * EMB);
    wsplit_t<<<dim3(16, 16, 4), 256>>>(wq, wk, wv, wu, wth, wtl);

    // 2) fused HMMA Q/K/V projection: one 8192 x 1536 x 512 GEMM
    cudaFuncSetAttribute(proj_mma, cudaFuncAttributeMaxDynamicSharedMemorySize,
                         MMA2_SMEM);
    proj_mma<<<dim3(12, MROWS / 256), 256, MMA2_SMEM>>>(
        xh, xl, wth, wtl, qh, ql, kh, kl, vh, vl);

    // 3a) local-window attention -> unnormalized partial + (max, sum)
    cudaFuncSetAttribute(attn_local, cudaFuncAttributeMaxDynamicSharedMemorySize,
                         ATTN_SMEM);
    attn_local<<<dim3(SEQ / 64, HEADS, BSZ), 256, ATTN_SMEM>>>(
        qh, ql, kh, kl, vh, vl, ol, ml, sl);

    // 3b) strided attention + combine -> ah/al
    attn_strided<<<dim3(64, HEADS, BSZ), 128>>>(
        qh, ql, kh, kl, vh, vl, ol, ml, sl, ah, al);

    // 4) HMMA unify projection (+bias)
    cudaFuncSetAttribute(unify_mma, cudaFuncAttributeMaxDynamicSharedMemorySize,
                         MMA2_SMEM);
    unify_mma<<<dim3(4, MROWS / 256), 256, MMA2_SMEM>>>(
        ah, al, wth, wtl, out, bu);
}

// round 15
// speedup vs baseline: 1.2394x; 1.2394x over previous
#include <cuda_runtime.h>
#include <cuda_fp16.h>
#include <cstdint>
#include <math.h>

#define BSZ 4
#define SEQ 2048
#define EMB 512
#define HEADS 8
#define HD 64
#define HH 512
#define MROWS (BSZ*SEQ)   // 8192
#define NEGINF (-1e30f)

// ---------------------------------------------------------------------------
// Scratch (device globals — no allocation allowed)
// ---------------------------------------------------------------------------
__device__ float g_ol[MROWS*HH];            // unnormalized local attention out
__device__ float g_ml[MROWS*HEADS];         // local row max
__device__ float g_sl[MROWS*HEADS];         // local row sum
__device__ __half g_qh[MROWS*HH];
__device__ __half g_ql[MROWS*HH];
__device__ __half g_kh[MROWS*HH];
__device__ __half g_kl[MROWS*HH];
__device__ __half g_vh[MROWS*HH];
__device__ __half g_vl[MROWS*HH];
__device__ __half g_xh[MROWS*EMB];
__device__ __half g_xl[MROWS*EMB];
__device__ __half g_ah[MROWS*HH];
__device__ __half g_al[MROWS*HH];
__device__ __half g_wth[4*EMB*HH];          // [wq,wk,wv,wu] transposed [N][K] fp16

// ---------------------------------------------------------------------------
// Helpers (base-ISA only: ldmatrix / mma.sync / cp.async)
// ---------------------------------------------------------------------------
__device__ __forceinline__ uint32_t smem_u32(const void* p) {
    uint32_t a;
    asm("{ .reg .u64 t; cvta.to.shared.u64 t, %1; cvt.u32.u64 %0, t; }"
        : "=r"(a) : "l"(p));
    return a;
}

#define LDSM4(r, addr) \
    asm volatile("ldmatrix.sync.aligned.m8n8.x4.shared.b16 {%0,%1,%2,%3}, [%4];" \
        : "=r"((r)[0]), "=r"((r)[1]), "=r"((r)[2]), "=r"((r)[3]) \
        : "r"(addr))

#define LDSM4T(r, addr) \
    asm volatile("ldmatrix.sync.aligned.m8n8.x4.trans.shared.b16 {%0,%1,%2,%3}, [%4];" \
        : "=r"((r)[0]), "=r"((r)[1]), "=r"((r)[2]), "=r"((r)[3]) \
        : "r"(addr))

__device__ __forceinline__ void mma_f16(float* d, const uint32_t* a,
                                        uint32_t b0, uint32_t b1) {
    asm volatile(
        "mma.sync.aligned.m16n8k16.row.col.f32.f16.f16.f32 "
        "{%0,%1,%2,%3}, {%4,%5,%6,%7}, {%8,%9}, {%0,%1,%2,%3};"
        : "+f"(d[0]), "+f"(d[1]), "+f"(d[2]), "+f"(d[3])
        : "r"(a[0]), "r"(a[1]), "r"(a[2]), "r"(a[3]), "r"(b0), "r"(b1));
}

#define CP_ASYNC16(dst, src) \
    asm volatile("cp.async.cg.shared.global [%0], [%1], 16;" \
                 :: "r"(dst), "l"(src))
#define CP_COMMIT() asm volatile("cp.async.commit_group;")

__device__ __forceinline__ __half2 split_hi(float a, float b) {
    __half2 h;
    h.x = __float2half_rn(a);
    h.y = __float2half_rn(b);
    return h;
}
__device__ __forceinline__ __half2 split_lo(float a, float b, __half2 h) {
    __half2 l;
    l.x = __float2half_rn(a - __half2float(h.x));
    l.y = __float2half_rn(b - __half2float(h.y));
    return l;
}

// ---------------------------------------------------------------------------
// fp16 split conversion (x only)
// ---------------------------------------------------------------------------
__global__ void __launch_bounds__(256) split_fp16_k(
    const float* __restrict__ in, __half* __restrict__ hi,
    __half* __restrict__ lo, int n)
{
    int i = (blockIdx.x * 256 + threadIdx.x) * 4;
    if (i >= n) return;
    float4 v = *(const float4*)(in + i);
    __half2 h0 = split_hi(v.x, v.y), h1 = split_hi(v.z, v.w);
    __half2 l0 = split_lo(v.x, v.y, h0), l1 = split_lo(v.z, v.w, h1);
    *(__half2*)(hi + i) = h0;
    *(__half2*)(hi + i + 2) = h1;
    *(__half2*)(lo + i) = l0;
    *(__half2*)(lo + i + 2) = l1;
}

// ---------------------------------------------------------------------------
// Weight transpose to fp16 (hi only — 2-pass GEMMs)
// ---------------------------------------------------------------------------
__global__ void __launch_bounds__(256) wsplit_t(
    const float* __restrict__ w0, const float* __restrict__ w1,
    const float* __restrict__ w2, const float* __restrict__ w3,
    __half* __restrict__ th)
{
    __shared__ float t[32][33];
    int z = blockIdx.z;
    const float* W = (z == 0) ? w0 : (z == 1) ? w1 : (z == 2) ? w2 : w3;
    __half* dh = th + (size_t)z * 512 * 512;
    int n0 = blockIdx.x * 32, k0 = blockIdx.y * 32;
    int tx = threadIdx.x & 31, ty = threadIdx.x >> 5;
    #pragma unroll
    for (int i = 0; i < 4; i++) {
        int r = ty + i * 8;
        t[r][tx] = W[(size_t)(k0 + r) * 512 + n0 + tx];
    }
    __syncthreads();
    #pragma unroll
    for (int i = 0; i < 4; i++) {
        int r = ty + i * 8;
        dh[(size_t)(n0 + r) * 512 + k0 + tx] = __float2half_rn(t[tx][r]);
    }
}

// ---------------------------------------------------------------------------
// 2-pass fp16 GEMM tile: C[128 m][128 n] = alpha*((Ah+Al)@Bh^T) (+bias)
// SMEM per stage: Ah | Al | Bh (128 rows x 80 B each); double-buffered.
// ---------------------------------------------------------------------------
#define BUF_B   10240              // 128 * 80
#define STG_B   (3 * BUF_B)        // 30720
#define MMA_SMEM (2 * STG_B)       // 61440

__device__ __forceinline__ void stage_load(
    uint32_t sdst,
    const __half* a0, const __half* a1, const __half* b0, int tid)
{
    const __half* srcs[3] = {a0, a1, b0};
    #pragma unroll
    for (int b = 0; b < 3; ++b) {
        uint32_t dst = sdst + b * BUF_B;
        #pragma unroll
        for (int it = 0; it < 2; ++it) {
            int idx = tid + it * 256;
            int r = idx >> 2, seg = idx & 3;
            CP_ASYNC16(dst + r * 80 + seg * 16,
                       __cvta_generic_to_global(srcs[b] + (size_t)r * 512 + seg * 8));
        }
    }
}

__device__ __forceinline__ void mma_gemm_128x128(
    const __half* __restrict__ Ah, const __half* __restrict__ Al,
    const __half* __restrict__ Bh,
    float* __restrict__ C, float alpha, const float* __restrict__ bias,
    int m0, int n0,
    __half* __restrict__ Ch, __half* __restrict__ Cl)
{
    extern __shared__ __align__(16) uint8_t smem[];
    const uint32_t sbase = smem_u32(smem);
    const int tid  = threadIdx.x;
    const int lane = tid & 31, wid = tid >> 5;
    const int wm = wid >> 1, wn = wid & 1;

    const __half* pAh = Ah + (size_t)m0 * 512;
    const __half* pAl = Al + (size_t)m0 * 512;
    const __half* pBh = Bh + (size_t)n0 * 512;

    float acc[2][8][4];
    #pragma unroll
    for (int mf = 0; mf < 2; mf++)
        #pragma unroll
        for (int nf = 0; nf < 8; nf++)
            #pragma unroll
            for (int j = 0; j < 4; j++) acc[mf][nf][j] = 0.f;

    const uint32_t aoff =
        (uint32_t)(wm * 32 + (lane & 15)) * 80 + (lane >> 4) * 16;
    const uint32_t boff =
        (uint32_t)(wn * 64 + (lane & 7) + ((lane >> 3) & 1) * 8) * 80
        + (lane >> 4) * 16;

    stage_load(sbase, pAh, pAl, pBh, tid);
    CP_COMMIT();

    for (int c = 0; c < 16; ++c) {
        if (c < 15) {
            stage_load(sbase + ((c + 1) & 1) * STG_B,
                       pAh + (c + 1) * 32, pAl + (c + 1) * 32,
                       pBh + (c + 1) * 32, tid);
            CP_COMMIT();
            asm volatile("cp.async.wait_group 1;");
        } else {
            asm volatile("cp.async.wait_group 0;");
        }
        __syncthreads();

        const uint32_t st = sbase + (c & 1) * STG_B;
        #pragma unroll
        for (int t = 0; t < 2; ++t) {
            const uint32_t ka = t * 32;
            uint32_t a_h[2][4], a_l[2][4], bb[4][4];

            LDSM4(a_h[0], st + aoff + ka);
            LDSM4(a_h[1], st + aoff + 16 * 80 + ka);
            #pragma unroll
            for (int g = 0; g < 4; ++g)
                LDSM4(bb[g], st + 2 * BUF_B + boff + g * 16 * 80 + ka);

            // P1: Ah @ Bh
            #pragma unroll
            for (int mf = 0; mf < 2; ++mf)
                #pragma unroll
                for (int nf = 0; nf < 8; ++nf)
                    mma_f16(acc[mf][nf], a_h[mf],
                            bb[nf >> 1][nf & 1], bb[nf >> 1][2 + (nf & 1)]);

            // P2: Al @ Bh
            LDSM4(a_l[0], st + BUF_B + aoff + ka);
            LDSM4(a_l[1], st + BUF_B + aoff + 16 * 80 + ka);
            #pragma unroll
            for (int mf = 0; mf < 2; ++mf)
                #pragma unroll
                for (int nf = 0; nf < 8; ++nf)
                    mma_f16(acc[mf][nf], a_l[mf],
                            bb[nf >> 1][nf & 1], bb[nf >> 1][2 + (nf & 1)]);
        }
        __syncthreads();
    }

    #pragma unroll
    for (int mf = 0; mf < 2; ++mf) {
        const int r0 = m0 + wm * 32 + mf * 16 + (lane >> 2);
        #pragma unroll
        for (int nf = 0; nf < 8; ++nf) {
            const int col = n0 + wn * 64 + nf * 8 + (lane & 3) * 2;
            float bx = 0.f, by = 0.f;
            if (bias) { bx = bias[col]; by = bias[col + 1]; }
            float2 v0 = make_float2(acc[mf][nf][0] * alpha + bx,
                                    acc[mf][nf][1] * alpha + by);
            float2 v1 = make_float2(acc[mf][nf][2] * alpha + bx,
                                    acc[mf][nf][3] * alpha + by);
            if (C) {
                *(float2*)(C + (size_t)r0 * 512 + col) = v0;
                *(float2*)(C + (size_t)(r0 + 8) * 512 + col) = v1;
            }
            if (Ch) {
                __half2 hh = split_hi(v0.x, v0.y);
                *(__half2*)(Ch + (size_t)r0 * 512 + col) = hh;
                *(__half2*)(Cl + (size_t)r0 * 512 + col) = split_lo(v0.x, v0.y, hh);
                hh = split_hi(v1.x, v1.y);
                *(__half2*)(Ch + (size_t)(r0 + 8) * 512 + col) = hh;
                *(__half2*)(Cl + (size_t)(r0 + 8) * 512 + col) = split_lo(v1.x, v1.y, hh);
            }
        }
    }
}

__global__ void __launch_bounds__(256) proj_mma(
    const __half* __restrict__ xh, const __half* __restrict__ xl,
    const __half* __restrict__ wth,
    __half* qh, __half* ql, __half* kh, __half* kl, __half* vh, __half* vl)
{
    int z = blockIdx.z;
    const __half* bh = wth + (size_t)z * 512 * 512;
    __half* Ch = (z == 0) ? qh : (z == 1) ? kh : vh;
    __half* Cl = (z == 0) ? ql : (z == 1) ? kl : vl;
    float alpha = (z == 2) ? 1.0f : 0.125f;      // 64^-0.5 on q and k
    mma_gemm_128x128(xh, xl, bh, nullptr, alpha, nullptr,
                     blockIdx.y * 128, blockIdx.x * 128, Ch, Cl);
}

__global__ void __launch_bounds__(256) unify_mma(
    const __half* __restrict__ ah, const __half* __restrict__ al,
    const __half* __restrict__ wth,
    float* __restrict__ out, const float* __restrict__ bias)
{
    mma_gemm_128x128(ah, al, wth + 3ull * 512 * 512,
                     out, 1.0f, bias, blockIdx.y * 128, blockIdx.x * 128,
                     nullptr, nullptr);
}

// ---------------------------------------------------------------------------
// Local-window attention (HMMA fp16, 3 split passes — full precision kept).
// Writes UNNORMALIZED O_local (fp32) + per-row (max, sum).
// ---------------------------------------------------------------------------
#define SM_QH      0         // 64 x 72 fp16 (stride 144B)
#define SM_QL      9216
#define SM_KH      18432     // 128 x 72 | later Ph 64 x 136 (272B)
#define SM_KL      36864
#define SM_VH      55296
#define SM_VL      73728
#define SM_REDMAX  92160     // fp32 [64][4]
#define SM_REDSUM  93184     // fp32 [64][4]
#define ATTN_SMEM  94208

__global__ void __launch_bounds__(256, 2) attn_local(
    const __half* __restrict__ qh, const __half* __restrict__ ql,
    const __half* __restrict__ kh, const __half* __restrict__ kl,
    const __half* __restrict__ vh, const __half* __restrict__ vl,
    float* __restrict__ Ol, float* __restrict__ Ml, float* __restrict__ Sl)
{
    extern __shared__ __align__(16) char smraw[];
    const uint32_t sb = smem_u32(smraw);
    const int qt   = blockIdx.x;
    const int h    = blockIdx.y;
    const int b    = blockIdx.z;
    const int base = qt * 64;
    const int tid  = threadIdx.x;
    const int lane = tid & 31, wid = tid >> 5;
    const int wm = wid >> 2, wn = wid & 3;

    float* REDMAX = (float*)(smraw + SM_REDMAX);
    float* REDSUM = (float*)(smraw + SM_REDSUM);

    #define ROWOFF(p) ((size_t)((b * SEQ + (p)) * HEADS + h) * HD)

    for (int idx = tid; idx < 1024; idx += 256) {
        int buf = idx >> 9, rem = idx & 511;
        int i = rem >> 3, seg = rem & 7;
        const __half* src = (buf ? ql : qh) + ROWOFF(base + i) + seg * 8;
        CP_ASYNC16(sb + SM_QH + buf * 9216 + i * 144 + seg * 16,
                   __cvta_generic_to_global(src));
    }
    for (int idx = tid; idx < 4096; idx += 256) {
        int buf = idx >> 10, rem = idx & 1023;
        int t = rem >> 3, seg = rem & 7;
        int key = base - 64 + t;
        uint32_t dstoff = (buf == 0 ? SM_KH : buf == 1 ? SM_KL :
                           buf == 2 ? SM_VH : SM_VL) + t * 144 + seg * 16;
        if (key >= 0) {
            const __half* src =
                (buf == 0 ? kh : buf == 1 ? kl : buf == 2 ? vh : vl)
                + ROWOFF(key) + seg * 8;
            CP_ASYNC16(sb + dstoff, __cvta_generic_to_global(src));
        } else {
            *(uint4*)(smraw + dstoff) = make_uint4(0, 0, 0, 0);
        }
    }
    CP_COMMIT();
    asm volatile("cp.async.wait_group 0;");
    __syncthreads();

    // S = Q @ Kwin^T (3 split passes)
    float accs[2][4][4];
    #pragma unroll
    for (int mf = 0; mf < 2; mf++)
        #pragma unroll
        for (int nf = 0; nf < 4; nf++)
            #pragma unroll
            for (int j = 0; j < 4; j++) accs[mf][nf][j] = 0.f;

    const uint32_t aQrow = (uint32_t)(wm * 32 + (lane & 15)) * 144
                         + (lane >> 4) * 16;
    const uint32_t bKrow = (uint32_t)(wn * 32 + (lane & 7)
                         + ((lane >> 3) & 1) * 8) * 144 + (lane >> 4) * 16;

    #pragma unroll
    for (int kd = 0; kd < 4; kd++) {
        const uint32_t ka = kd * 32;
        uint32_t a_h[2][4], a_l[2][4], bh4[2][4], bl4[2][4];
        LDSM4(a_h[0], sb + SM_QH + aQrow + ka);
        LDSM4(a_h[1], sb + SM_QH + aQrow + 16 * 144 + ka);
        LDSM4(a_l[0], sb + SM_QL + aQrow + ka);
        LDSM4(a_l[1], sb + SM_QL + aQrow + 16 * 144 + ka);
        #pragma unroll
        for (int g = 0; g < 2; g++) {
            LDSM4(bh4[g], sb + SM_KH + bKrow + g * 16 * 144 + ka);
            LDSM4(bl4[g], sb + SM_KL + bKrow + g * 16 * 144 + ka);
        }
        #pragma unroll
        for (int mf = 0; mf < 2; mf++)
            #pragma unroll
            for (int nf = 0; nf < 4; nf++) {
                mma_f16(accs[mf][nf], a_h[mf],
                        bh4[nf >> 1][nf & 1], bh4[nf >> 1][2 + (nf & 1)]);
                mma_f16(accs[mf][nf], a_l[mf],
                        bh4[nf >> 1][nf & 1], bh4[nf >> 1][2 + (nf & 1)]);
                mma_f16(accs[mf][nf], a_h[mf],
                        bl4[nf >> 1][nf & 1], bl4[nf >> 1][2 + (nf & 1)]);
            }
    }

    // mask + per-warp row max
    #pragma unroll
    for (int mf = 0; mf < 2; mf++)
        #pragma unroll
        for (int rh = 0; rh < 2; rh++) {
            int q_l = wm * 32 + mf * 16 + rh * 8 + (lane >> 2);
            int tlo = (base == 0) ? 64 : q_l;
            int thi = q_l + 64;
            float m = NEGINF;
            #pragma unroll
            for (int nf = 0; nf < 4; nf++)
                #pragma unroll
                for (int c = 0; c < 2; c++) {
                    int t = wn * 32 + nf * 8 + (lane & 3) * 2 + c;
                    float& sv = accs[mf][nf][rh * 2 + c];
                    if (t < tlo || t > thi) sv = NEGINF;
                    m = fmaxf(m, sv);
                }
            m = fmaxf(m, __shfl_xor_sync(0xffffffffu, m, 1));
            m = fmaxf(m, __shfl_xor_sync(0xffffffffu, m, 2));
            if ((lane & 3) == 0) REDMAX[q_l * 4 + wn] = m;
        }
    __syncthreads();   // B1

    // exp fragments -> P fp16 hi/lo; row sums
    #pragma unroll
    for (int mf = 0; mf < 2; mf++)
        #pragma unroll
        for (int rh = 0; rh < 2; rh++) {
            int q_l = wm * 32 + mf * 16 + rh * 8 + (lane >> 2);
            float Mr = fmaxf(fmaxf(REDMAX[q_l * 4 + 0], REDMAX[q_l * 4 + 1]),
                             fmaxf(REDMAX[q_l * 4 + 2], REDMAX[q_l * 4 + 3]));
            float rsum = 0.f;
            #pragma unroll
            for (int nf = 0; nf < 4; nf++) {
                float p0 = __expf(accs[mf][nf][rh * 2 + 0] - Mr);
                float p1 = __expf(accs[mf][nf][rh * 2 + 1] - Mr);
                rsum += p0 + p1;
                int t0 = wn * 32 + nf * 8 + (lane & 3) * 2;
                uint32_t addr = (uint32_t)q_l * 272 + t0 * 2;
                __half2 hh = split_hi(p0, p1);
                *(__half2*)(smraw + SM_KH + addr) = hh;
                *(__half2*)(smraw + SM_KL + addr) = split_lo(p0, p1, hh);
            }
            rsum += __shfl_xor_sync(0xffffffffu, rsum, 1);
            rsum += __shfl_xor_sync(0xffffffffu, rsum, 2);
            if ((lane & 3) == 0) REDSUM[q_l * 4 + wn] = rsum;
        }
    __syncthreads();   // B2

    // O = P @ Vwin (3 split passes)
    float acco[2][2][4];
    #pragma unroll
    for (int mf = 0; mf < 2; mf++)
        #pragma unroll
        for (int nf = 0; nf < 2; nf++)
            #pragma unroll
            for (int j = 0; j < 4; j++) acco[mf][nf][j] = 0.f;

    const uint32_t aProw = (uint32_t)(wm * 32 + (lane & 15)) * 272
                         + (lane >> 4) * 16;
    const uint32_t bVcol = (uint32_t)(wn * 16 + (lane >> 4) * 8) * 2;

    #pragma unroll
    for (int kt = 0; kt < 8; kt++) {
        uint32_t pa_h[2][4], pa_l[2][4], vbh[4], vbl[4];
        LDSM4(pa_h[0], sb + SM_KH + aProw + kt * 32);
        LDSM4(pa_h[1], sb + SM_KH + aProw + 16 * 272 + kt * 32);
        LDSM4(pa_l[0], sb + SM_KL + aProw + kt * 32);
        LDSM4(pa_l[1], sb + SM_KL + aProw + 16 * 272 + kt * 32);
        uint32_t vrow = (uint32_t)(kt * 16 + (lane & 15)) * 144 + bVcol;
        LDSM4T(vbh, sb + SM_VH + vrow);
        LDSM4T(vbl, sb + SM_VL + vrow);
        #pragma unroll
        for (int mf = 0; mf < 2; mf++) {
            mma_f16(acco[mf][0], pa_h[mf], vbh[0], vbh[1]);
            mma_f16(acco[mf][1], pa_h[mf], vbh[2], vbh[3]);
            mma_f16(acco[mf][0], pa_h[mf], vbl[0], vbl[1]);
            mma_f16(acco[mf][1], pa_h[mf], vbl[2], vbl[3]);
            mma_f16(acco[mf][0], pa_l[mf], vbh[0], vbh[1]);
            mma_f16(acco[mf][1], pa_l[mf], vbh[2], vbh[3]);
        }
    }

    // epilogue: write unnormalized O_local + per-row (max, sum)
    const int d0 = wn * 16 + (lane & 3) * 2;
    #pragma unroll
    for (int mf = 0; mf < 2; mf++)
        #pragma unroll
        for (int rh = 0; rh < 2; rh++) {
            int q_l = wm * 32 + mf * 16 + rh * 8 + (lane >> 2);
            int qpos = base + q_l;
            if (wn == 0 && (lane & 3) == 0) {
                float Mr = fmaxf(fmaxf(REDMAX[q_l * 4 + 0], REDMAX[q_l * 4 + 1]),
                                 fmaxf(REDMAX[q_l * 4 + 2], REDMAX[q_l * 4 + 3]));
                float sum = REDSUM[q_l * 4 + 0] + REDSUM[q_l * 4 + 1]
                          + REDSUM[q_l * 4 + 2] + REDSUM[q_l * 4 + 3];
                int gi = (b * SEQ + qpos) * HEADS + h;
                Ml[gi] = Mr;
                Sl[gi] = sum;
            }
            size_t off = ROWOFF(qpos) + d0;
            *(float2*)(Ol + off) =
                make_float2(acco[mf][0][rh * 2 + 0], acco[mf][0][rh * 2 + 1]);
            *(float2*)(Ol + off + 8) =
                make_float2(acco[mf][1][rh * 2 + 0], acco[mf][1][rh * 2 + 1]);
        }
    #undef ROWOFF
}

// ---------------------------------------------------------------------------
// Strided attention + flash-combine. Block = (residue r, head, batch).
// ---------------------------------------------------------------------------
#define ST_QH    0       // 32 x 72 fp16 (144B stride)
#define ST_QL    4608
#define ST_KH    9216
#define ST_KL    13824
#define ST_VH    18432
#define ST_VL    23040
#define ST_PH    27648   // 32 x 40 fp16 (80B stride)
#define ST_PL    30208
#define ST_RMAX  32768   // fp32 [32][4]
#define ST_RSUM  33280   // fp32 [32][4]
#define ST_TOTAL 33792

__global__ void __launch_bounds__(128) attn_strided(
    const __half* __restrict__ qh, const __half* __restrict__ ql,
    const __half* __restrict__ kh, const __half* __restrict__ kl,
    const __half* __restrict__ vh, const __half* __restrict__ vl,
    const float* __restrict__ Ol, const float* __restrict__ Ml,
    const float* __restrict__ Sl,
    __half* __restrict__ outh, __half* __restrict__ outl)
{
    __shared__ __align__(16) char ss[ST_TOTAL];
    const uint32_t sb = smem_u32(ss);
    const int r = blockIdx.x, h = blockIdx.y, b = blockIdx.z;
    const int tid = threadIdx.x, lane = tid & 31, wn = tid >> 5;

    float* RMAX = (float*)(ss + ST_RMAX);
    float* RSUM = (float*)(ss + ST_RSUM);

    #define ROWOFF(p) ((size_t)((b * SEQ + (p)) * HEADS + h) * HD)

    for (int idx = tid; idx < 1536; idx += 128) {
        int buf = idx >> 8, rem = idx & 255;
        int j = rem >> 3, seg = rem & 7;
        const __half* bp =
            buf == 0 ? qh : buf == 1 ? ql : buf == 2 ? kh :
            buf == 3 ? kl : buf == 4 ? vh : vl;
        CP_ASYNC16(sb + buf * 4608 + j * 144 + seg * 16,
                   __cvta_generic_to_global(bp + ROWOFF(64 * j + r) + seg * 8));
    }
    CP_COMMIT();
    asm volatile("cp.async.wait_group 0;");
    __syncthreads();

    float accs[2][4];
    #pragma unroll
    for (int mf = 0; mf < 2; mf++)
        #pragma unroll
        for (int j = 0; j < 4; j++) accs[mf][j] = 0.f;

    const uint32_t aQrow = (uint32_t)(lane & 15) * 144 + (lane >> 4) * 16;
    const uint32_t bKrow = (uint32_t)(wn * 8 + (lane & 7)) * 144
                         + (lane >> 3) * 16;

    uint32_t bh4[2][4], bl4[2][4];
    LDSM4(bh4[0], sb + ST_KH + bKrow);
    LDSM4(bh4[1], sb + ST_KH + bKrow + 64);
    LDSM4(bl4[0], sb + ST_KL + bKrow);
    LDSM4(bl4[1], sb + ST_KL + bKrow + 64);

    #pragma unroll
    for (int kd = 0; kd < 4; kd++) {
        uint32_t a_h[2][4], a_l[2][4];
        LDSM4(a_h[0], sb + ST_QH + aQrow + kd * 32);
        LDSM4(a_h[1], sb + ST_QH + aQrow + 16 * 144 + kd * 32);
        LDSM4(a_l[0], sb + ST_QL + aQrow + kd * 32);
        LDSM4(a_l[1], sb + ST_QL + aQrow + 16 * 144 + kd * 32);
        uint32_t b0h = bh4[kd >> 1][(kd & 1) * 2];
        uint32_t b1h = bh4[kd >> 1][(kd & 1) * 2 + 1];
        uint32_t b0l = bl4[kd >> 1][(kd & 1) * 2];
        uint32_t b1l = bl4[kd >> 1][(kd & 1) * 2 + 1];
        #pragma unroll
        for (int mf = 0; mf < 2; mf++) {
            mma_f16(accs[mf], a_h[mf], b0h, b1h);
            mma_f16(accs[mf], a_l[mf], b0h, b1h);
            mma_f16(accs[mf], a_h[mf], b0l, b1l);
        }
    }

    #pragma unroll
    for (int mf = 0; mf < 2; mf++)
        #pragma unroll
        for (int rh = 0; rh < 2; rh++) {
            int j = mf * 16 + rh * 8 + (lane >> 2);
            float m = NEGINF;
            #pragma unroll
            for (int c = 0; c < 2; c++) {
                int i = wn * 8 + (lane & 3) * 2 + c;
                float& sv = accs[mf][rh * 2 + c];
                if (i > j - 2) sv = NEGINF;
                m = fmaxf(m, sv);
            }
            m = fmaxf(m, __shfl_xor_sync(0xffffffffu, m, 1));
            m = fmaxf(m, __shfl_xor_sync(0xffffffffu, m, 2));
            if ((lane & 3) == 0) RMAX[j * 4 + wn] = m;
        }
    __syncthreads();

    #pragma unroll
    for (int mf = 0; mf < 2; mf++)
        #pragma unroll
        for (int rh = 0; rh < 2; rh++) {
            int j = mf * 16 + rh * 8 + (lane >> 2);
            float Ms = fmaxf(fmaxf(RMAX[j * 4 + 0], RMAX[j * 4 + 1]),
                             fmaxf(RMAX[j * 4 + 2], RMAX[j * 4 + 3]));
            int i0 = wn * 8 + (lane & 3) * 2;
            float p0 = (i0 <= j - 2)
                     ? __expf(accs[mf][rh * 2 + 0] - Ms) : 0.f;
            float p1 = (i0 + 1 <= j - 2)
                     ? __expf(accs[mf][rh * 2 + 1] - Ms) : 0.f;
            float rsum = p0 + p1;
            uint32_t addr = (uint32_t)j * 80 + i0 * 2;
            __half2 hh = split_hi(p0, p1);
            *(__half2*)(ss + ST_PH + addr) = hh;
            *(__half2*)(ss + ST_PL + addr) = split_lo(p0, p1, hh);
            rsum += __shfl_xor_sync(0xffffffffu, rsum, 1);
            rsum += __shfl_xor_sync(0xffffffffu, rsum, 2);
            if ((lane & 3) == 0) RSUM[j * 4 + wn] = rsum;
        }
    __syncthreads();

    float acco[2][2][4];
    #pragma unroll
    for (int mf = 0; mf < 2; mf++)
        #pragma unroll
        for (int nf = 0; nf < 2; nf++)
            #pragma unroll
            for (int j = 0; j < 4; j++) acco[mf][nf][j] = 0.f;

    const uint32_t aProw = (uint32_t)(lane & 15) * 80 + (lane >> 4) * 16;
    const uint32_t bVcol = (uint32_t)(wn * 16 + (lane >> 4) * 8) * 2;

    #pragma unroll
    for (int kt = 0; kt < 2; kt++) {
        uint32_t pa_h[2][4], pa_l[2][4], vbh[4], vbl[4];
        LDSM4(pa_h[0], sb + ST_PH + aProw + kt * 32);
        LDSM4(pa_h[1], sb + ST_PH + aProw + 16 * 80 + kt * 32);
        LDSM4(pa_l[0], sb + ST_PL + aProw + kt * 32);
        LDSM4(pa_l[1], sb + ST_PL + aProw + 16 * 80 + kt * 32);
        uint32_t vrow = (uint32_t)(kt * 16 + (lane & 15)) * 144 + bVcol;
        LDSM4T(vbh, sb + ST_VH + vrow);
        LDSM4T(vbl, sb + ST_VL + vrow);
        #pragma unroll
        for (int mf = 0; mf < 2; mf++) {
            mma_f16(acco[mf][0], pa_h[mf], vbh[0], vbh[1]);
            mma_f16(acco[mf][1], pa_h[mf], vbh[2], vbh[3]);
            mma_f16(acco[mf][0], pa_h[mf], vbl[0], vbl[1]);
            mma_f16(acco[mf][1], pa_h[mf], vbl[2], vbl[3]);
            mma_f16(acco[mf][0], pa_l[mf], vbh[0], vbh[1]);
            mma_f16(acco[mf][1], pa_l[mf], vbh[2], vbh[3]);
        }
    }

    #pragma unroll
    for (int mf = 0; mf < 2; mf++)
        #pragma unroll
        for (int rh = 0; rh < 2; rh++) {
            int j = mf * 16 + rh * 8 + (lane >> 2);
            int qpos = 64 * j + r;
            float m_s = fmaxf(fmaxf(RMAX[j * 4 + 0], RMAX[j * 4 + 1]),
                              fmaxf(RMAX[j * 4 + 2], RMAX[j * 4 + 3]));
            float s_s = RSUM[j * 4 + 0] + RSUM[j * 4 + 1]
                      + RSUM[j * 4 + 2] + RSUM[j * 4 + 3];
            int gi = (b * SEQ + qpos) * HEADS + h;
            float m_l = Ml[gi], s_l = Sl[gi];
            float M = fmaxf(m_l, m_s);
            float fl = __expf(m_l - M);
            float fs = __expf(m_s - M);
            float inv = 1.f / (s_l * fl + s_s * fs);
            #pragma unroll
            for (int nf = 0; nf < 2; nf++) {
                int d0 = wn * 16 + nf * 8 + (lane & 3) * 2;
                size_t off = ROWOFF(qpos) + d0;
                float2 olv = *(const float2*)(Ol + off);
                float o0 = (olv.x * fl + acco[mf][nf][rh * 2 + 0] * fs) * inv;
                float o1 = (olv.y * fl + acco[mf][nf][rh * 2 + 1] * fs) * inv;
                __half2 hh = split_hi(o0, o1);
                *(__half2*)(outh + off) = hh;
                *(__half2*)(outl + off) = split_lo(o0, o1, hh);
            }
        }
    #undef ROWOFF
}

// ---------------------------------------------------------------------------
extern "C" void kernel_launch(void* const* d_in, const int* in_sizes, int n_in,
                              void* d_out, int out_size)
{
    const float* x  = (const float*)d_in[0];
    const float* wk = (const float*)d_in[1];
    const float* wq = (const float*)d_in[2];
    const float* wv = (const float*)d_in[3];
    const float* wu = (const float*)d_in[4];
    const float* bu = (const float*)d_in[5];
    float* out = (float*)d_out;

    float *ol, *ml, *sl;
    __half *xh, *xl, *ah, *al, *wth;
    __half *qh, *ql, *kh, *kl, *vh, *vl;
    cudaGetSymbolAddress((void**)&ol,  g_ol);
    cudaGetSymbolAddress((void**)&ml,  g_ml);
    cudaGetSymbolAddress((void**)&sl,  g_sl);
    cudaGetSymbolAddress((void**)&xh,  g_xh);
    cudaGetSymbolAddress((void**)&xl,  g_xl);
    cudaGetSymbolAddress((void**)&ah,  g_ah);
    cudaGetSymbolAddress((void**)&al,  g_al);
    cudaGetSymbolAddress((void**)&wth, g_wth);
    cudaGetSymbolAddress((void**)&qh,  g_qh);
    cudaGetSymbolAddress((void**)&ql,  g_ql);
    cudaGetSymbolAddress((void**)&kh,  g_kh);
    cudaGetSymbolAddress((void**)&kl,  g_kl);
    cudaGetSymbolAddress((void**)&vh,  g_vh);
    cudaGetSymbolAddress((void**)&vl,  g_vl);

    // 1) split x to fp16 hi/lo; transpose weights to fp16
    split_fp16_k<<<(MROWS * EMB) / 1024, 256>>>(x, xh, xl, MROWS * EMB);
    wsplit_t<<<dim3(16, 16, 4), 256>>>(wq, wk, wv, wu, wth);

    // 2) 2-pass fp16 HMMA Q/K/V projections
    cudaFuncSetAttribute(proj_mma, cudaFuncAttributeMaxDynamicSharedMemorySize,
                         MMA_SMEM);
    proj_mma<<<dim3(HH / 128, MROWS / 128, 3), 256, MMA_SMEM>>>(
        xh, xl, wth, qh, ql, kh, kl, vh, vl);

    // 3a) local-window attention (3-pass, full precision)
    cudaFuncSetAttribute(attn_local, cudaFuncAttributeMaxDynamicSharedMemorySize,
                         ATTN_SMEM);
    attn_local<<<dim3(SEQ / 64, HEADS, BSZ), 256, ATTN_SMEM>>>(
        qh, ql, kh, kl, vh, vl, ol, ml, sl);

    // 3b) strided attention + combine -> ah/al
    attn_strided<<<dim3(64, HEADS, BSZ), 128>>>(
        qh, ql, kh, kl, vh, vl, ol, ml, sl, ah, al);

    // 4) 2-pass fp16 HMMA unify projection (+bias)
    cudaFuncSetAttribute(unify_mma, cudaFuncAttributeMaxDynamicSharedMemorySize,
                         MMA_SMEM);
    unify_mma<<<dim3(EMB / 128, MROWS / 128), 256, MMA_SMEM>>>(
        ah, al, wth, out, bu);
}